// round 4
// baseline (speedup 1.0000x reference)
#include <cuda_runtime.h>
#include <cuda_fp16.h>

#define NT      250000
#define NNODES  20000
#define EMB     64
#define NC      16
#define NRP     (NNODES*8)
#define W1SCALE 256.0f
#define W1INV   (1.0f/256.0f)

// ---------------- scratch ---------------------------------------------------
__device__ __align__(16) float g_l1[NT*8];       // raw l1
__device__ __align__(16) float g_l2[NT*8];       // softmaxed l2
__device__ float g_colsum[NRP];
__device__ float g_rowsum[NRP];
__device__ __align__(16) float g_invC[NRP];      // [o][p] = 1/colsum[o*p]
__device__ __align__(16) float g_invR[NRP];      // [s][p] = 1/max(rowsum[s*p],1e-6)
__device__ __align__(16) float g_h[NNODES*EMB];
__device__ __align__(16) __half g_w1hf[NRP*EMB]; // fp16 copy of weights1 * 256
__device__ int   g_cnt_s[NNODES];
__device__ int   g_off_s[NNODES+1];
__device__ int   g_cur_s[NNODES];
__device__ int   g_perm_s[NT];
__device__ float g_out0[64*16];                  // striped partials for p=0 logits

__device__ __forceinline__ float H2F(__half v) { return __half2float(v); }

// ---------------- K0: zero everything + init logits + convert W1 -> fp16 ----
__global__ void k0_init(float* __restrict__ out, const float* __restrict__ bias2,
                        const float* __restrict__ W1) {
    int i = blockIdx.x * blockDim.x + threadIdx.x;
    int stride = gridDim.x * blockDim.x;
    for (int j = i; j < NRP; j += stride) { g_colsum[j] = 0.f; g_rowsum[j] = 0.f; }
    for (int j = i; j < NNODES; j += stride) g_cnt_s[j] = 0;
    for (int j = i; j < NNODES*NC; j += stride) out[j] = bias2[j & (NC-1)];
    for (int j = i; j < 64*16; j += stride) g_out0[j] = 0.f;
    const float4* w4 = (const float4*)W1;
    __half2* dst = (__half2*)g_w1hf;
    for (int j = i; j < (NRP*EMB)/4; j += stride) {
        float4 w = w4[j];
        dst[j*2]   = __floats2half2_rn(w.x * W1SCALE, w.y * W1SCALE);
        dst[j*2+1] = __floats2half2_rn(w.z * W1SCALE, w.w * W1SCALE);
    }
}

// ---------------- K1: GEMMs + softmax + colsum/rowsum atomics + s-hist ------
__global__ __launch_bounds__(256) void k1_l1l2(
    const float* __restrict__ rm,
    const float* __restrict__ Wl1, const float* __restrict__ bl1,
    const float* __restrict__ Wl2, const float* __restrict__ bl2,
    const int* __restrict__ hrow, const int* __restrict__ vcol)
{
    __shared__ float4 sW14[128], sW24[128];
    __shared__ float sb1[8], sb2[8];
    int tid = threadIdx.x;
    if (tid < 128) { sW14[tid] = ((const float4*)Wl1)[tid]; sW24[tid] = ((const float4*)Wl2)[tid]; }
    if (tid < 8) { sb1[tid] = bl1[tid]; sb2[tid] = bl2[tid]; }
    __syncthreads();

    const float4* rm4 = (const float4*)rm;
    int r0 = blockIdx.x * 512 + tid;

    float a1[2][8], a2[2][8];
#pragma unroll
    for (int rr = 0; rr < 2; rr++)
#pragma unroll
        for (int p = 0; p < 8; p++) { a1[rr][p] = sb1[p]; a2[rr][p] = sb2[p]; }

    for (int k4 = 0; k4 < 16; k4++) {
        float4 x[2];
#pragma unroll
        for (int rr = 0; rr < 2; rr++) {
            int row = r0 + rr * 256;
            x[rr] = (row < NT) ? rm4[(size_t)row * 16 + k4] : make_float4(0.f,0.f,0.f,0.f);
        }
#pragma unroll
        for (int j = 0; j < 4; j++) {
            int k = k4 * 4 + j;
            float4 w1lo = sW14[k*2], w1hi = sW14[k*2+1];
            float4 w2lo = sW24[k*2], w2hi = sW24[k*2+1];
#pragma unroll
            for (int rr = 0; rr < 2; rr++) {
                float xv = (j == 0) ? x[rr].x : (j == 1) ? x[rr].y : (j == 2) ? x[rr].z : x[rr].w;
                a1[rr][0] = fmaf(xv, w1lo.x, a1[rr][0]);
                a1[rr][1] = fmaf(xv, w1lo.y, a1[rr][1]);
                a1[rr][2] = fmaf(xv, w1lo.z, a1[rr][2]);
                a1[rr][3] = fmaf(xv, w1lo.w, a1[rr][3]);
                a1[rr][4] = fmaf(xv, w1hi.x, a1[rr][4]);
                a1[rr][5] = fmaf(xv, w1hi.y, a1[rr][5]);
                a1[rr][6] = fmaf(xv, w1hi.z, a1[rr][6]);
                a1[rr][7] = fmaf(xv, w1hi.w, a1[rr][7]);
                a2[rr][0] = fmaf(xv, w2lo.x, a2[rr][0]);
                a2[rr][1] = fmaf(xv, w2lo.y, a2[rr][1]);
                a2[rr][2] = fmaf(xv, w2lo.z, a2[rr][2]);
                a2[rr][3] = fmaf(xv, w2lo.w, a2[rr][3]);
                a2[rr][4] = fmaf(xv, w2hi.x, a2[rr][4]);
                a2[rr][5] = fmaf(xv, w2hi.y, a2[rr][5]);
                a2[rr][6] = fmaf(xv, w2hi.z, a2[rr][6]);
                a2[rr][7] = fmaf(xv, w2hi.w, a2[rr][7]);
            }
        }
    }

    float p0l1 = 0.f, p0l2 = 0.f;
#pragma unroll
    for (int rr = 0; rr < 2; rr++) {
        int row = r0 + rr * 256;
        if (row >= NT) continue;
        float m = a2[rr][0];
#pragma unroll
        for (int p = 1; p < 8; p++) m = fmaxf(m, a2[rr][p]);
        float e[8], ssum = 0.f;
#pragma unroll
        for (int p = 0; p < 8; p++) { e[p] = __expf(a2[rr][p] - m); ssum += e[p]; }
        float inv = 1.f / ssum;
#pragma unroll
        for (int p = 0; p < 8; p++) e[p] *= inv;

        float4* d1 = (float4*)(g_l1 + (size_t)row * 8);
        float4* d2 = (float4*)(g_l2 + (size_t)row * 8);
        d1[0] = make_float4(a1[rr][0], a1[rr][1], a1[rr][2], a1[rr][3]);
        d1[1] = make_float4(a1[rr][4], a1[rr][5], a1[rr][6], a1[rr][7]);
        d2[0] = make_float4(e[0], e[1], e[2], e[3]);
        d2[1] = make_float4(e[4], e[5], e[6], e[7]);

        int o = vcol[row], s = hrow[row];
        p0l1 += a1[rr][0];
        p0l2 += e[0];
#pragma unroll
        for (int p = 1; p < 8; p++) {
            atomicAdd(&g_colsum[o * p], a1[rr][p]);
            atomicAdd(&g_rowsum[s * p], e[p]);
        }
        atomicAdd(&g_cnt_s[s], 1);
    }

    int lane = tid & 31, wid = tid >> 5;
#pragma unroll
    for (int d = 16; d > 0; d >>= 1) {
        p0l1 += __shfl_down_sync(0xffffffffu, p0l1, d);
        p0l2 += __shfl_down_sync(0xffffffffu, p0l2, d);
    }
    __shared__ float red1[8], red2[8];
    if (lane == 0) { red1[wid] = p0l1; red2[wid] = p0l2; }
    __syncthreads();
    if (tid == 0) {
        float s1 = 0.f, s2 = 0.f;
#pragma unroll
        for (int w = 0; w < 8; w++) { s1 += red1[w]; s2 += red2[w]; }
        atomicAdd(&g_colsum[0], s1);
        atomicAdd(&g_rowsum[0], s2);
    }
}

// ---------------- K3: fast 3-level shuffle scan (1 block) -------------------
__global__ __launch_bounds__(1024) void k3_scan() {
    int tid = threadIdx.x;
    const int CH = 20;
    int base = tid * CH;
    int loc[CH]; int sum = 0;
#pragma unroll
    for (int j = 0; j < CH; j++) {
        int idx = base + j;
        int v = (idx < NNODES) ? g_cnt_s[idx] : 0;
        loc[j] = v; sum += v;
    }
    int lane = tid & 31, wid = tid >> 5;
    int x = sum;
#pragma unroll
    for (int d = 1; d < 32; d <<= 1) {
        int y = __shfl_up_sync(0xffffffffu, x, d);
        if (lane >= d) x += y;
    }
    __shared__ int wsum[32];
    if (lane == 31) wsum[wid] = x;
    __syncthreads();
    if (wid == 0) {
        int w = wsum[lane];
#pragma unroll
        for (int d = 1; d < 32; d <<= 1) {
            int y = __shfl_up_sync(0xffffffffu, w, d);
            if (lane >= d) w += y;
        }
        wsum[lane] = w;
    }
    __syncthreads();
    int run = x - sum + (wid ? wsum[wid - 1] : 0);
#pragma unroll
    for (int j = 0; j < CH; j++) {
        int idx = base + j;
        if (idx < NNODES) { g_off_s[idx] = run; g_cur_s[idx] = run; run += loc[j]; }
    }
    if (tid == 1023) g_off_s[NNODES] = wsum[31];
}

// ---------------- K45: scatter edges into CSR + build inverse tables --------
__global__ void k45_scatter_inv(const int* __restrict__ hrow) {
    int i = blockIdx.x * blockDim.x + threadIdx.x;
    int stride = gridDim.x * blockDim.x;
    for (int t = i; t < NT; t += stride) {
        int p = atomicAdd(&g_cur_s[hrow[t]], 1);
        g_perm_s[p] = t;
    }
    for (int j = i; j < NRP; j += stride) {
        int node = j >> 3, p = j & 7;
        g_invC[j] = 1.f / g_colsum[node * p];
        g_invR[j] = 1.f / fmaxf(g_rowsum[node * p], 1e-6f);
    }
}

// ---------------- K6: h[s] = relu(bias1 + sum_{t,p} l1n * W1[o*p]) ----------
__global__ __launch_bounds__(64) void k6_h(
    const int* __restrict__ vcol, const float* __restrict__ W1,
    const float* __restrict__ bias1)
{
    int s = blockIdx.x, e = threadIdx.x;
    int beg = g_off_s[s], end = g_off_s[s+1];
    __shared__ float sh_l[64][9];
    __shared__ int sh_ob[64];
    float accA = 0.f, accB = 0.f, acc0 = 0.f;
    for (int tile = beg; tile < end; tile += 64) {
        int n = min(64, end - tile);
        if (e < n) {
            int t = g_perm_s[tile + e];
            int o = vcol[t];
            sh_ob[e] = o * 64;
            const float4* lp = (const float4*)(g_l1 + (size_t)t * 8);
            const float4* ip = (const float4*)(g_invC + (size_t)o * 8);
            float4 a = lp[0], b = lp[1], ia = ip[0], ib = ip[1];
            sh_l[e][0] = a.x * ia.x; sh_l[e][1] = a.y * ia.y;
            sh_l[e][2] = a.z * ia.z; sh_l[e][3] = a.w * ia.w;
            sh_l[e][4] = b.x * ib.x; sh_l[e][5] = b.y * ib.y;
            sh_l[e][6] = b.z * ib.z; sh_l[e][7] = b.w * ib.w;
        }
        __syncthreads();
        for (int i = 0; i < n; i++) {
            int ob = sh_ob[i];
            acc0 += sh_l[i][0];                              // p=0 row handled at end
            accA = fmaf(sh_l[i][1], H2F(g_w1hf[ob     + e]), accA);
            accB = fmaf(sh_l[i][2], H2F(g_w1hf[ob*2   + e]), accB);
            accA = fmaf(sh_l[i][3], H2F(g_w1hf[ob*3   + e]), accA);
            accB = fmaf(sh_l[i][4], H2F(g_w1hf[ob*4   + e]), accB);
            accA = fmaf(sh_l[i][5], H2F(g_w1hf[ob*5   + e]), accA);
            accB = fmaf(sh_l[i][6], H2F(g_w1hf[ob*6   + e]), accB);
            accA = fmaf(sh_l[i][7], H2F(g_w1hf[ob*7   + e]), accA);
        }
        __syncthreads();
    }
    float acc = (accA + accB) * W1INV + acc0 * __ldg(&W1[e]); // undo x256; p=0 row fp32
    g_h[(size_t)s*64 + e] = fmaxf(acc + bias1[e], 0.f);
}

// ---------------- K7: fused h2 + einsum -> logits ---------------------------
__global__ __launch_bounds__(64) void k7_logits(
    const int* __restrict__ vcol, const float* __restrict__ W2,
    float* __restrict__ out)
{
    int s = blockIdx.x, tid = threadIdx.x;
    int beg = g_off_s[s], end = g_off_s[s+1];
    if (beg == end) return;
    __shared__ float sh_l[64][9];
    __shared__ int sh_o[64];
    float a[8] = {0.f,0.f,0.f,0.f,0.f,0.f,0.f,0.f};
    const float4* ir = (const float4*)(g_invR + (size_t)s * 8);
    float4 ia = ir[0], ib = ir[1];
    for (int tile = beg; tile < end; tile += 64) {
        int n = min(64, end - tile);
        if (tid < n) {
            int t = g_perm_s[tile + tid];
            int o = vcol[t];
            sh_o[tid] = o;
            const float4* lp = (const float4*)(g_l2 + (size_t)t * 8);
            float4 la = lp[0], lb = lp[1];
            sh_l[tid][0] = la.x * ia.x; sh_l[tid][1] = la.y * ia.y;
            sh_l[tid][2] = la.z * ia.z; sh_l[tid][3] = la.w * ia.w;
            sh_l[tid][4] = lb.x * ib.x; sh_l[tid][5] = lb.y * ib.y;
            sh_l[tid][6] = lb.z * ib.z; sh_l[tid][7] = lb.w * ib.w;
        }
        __syncthreads();
        for (int i = 0; i < n; i++) {
            float hv = g_h[(size_t)sh_o[i]*64 + tid];
#pragma unroll
            for (int p = 0; p < 8; p++) a[p] = fmaf(sh_l[i][p], hv, a[p]);
        }
        __syncthreads();
    }
    __shared__ float sh1[8][64];
#pragma unroll
    for (int p = 0; p < 8; p++) sh1[p][tid] = a[p];
    __syncthreads();
    int g = tid >> 4, c = tid & 15;
    float part[8];
#pragma unroll
    for (int p = 0; p < 8; p++) {
        int q = s * p; int r = q / NNODES;
        const float* w2 = W2 + r * (EMB*NC);
        float y = 0.f;
#pragma unroll
        for (int hh = 0; hh < 16; hh++)
            y = fmaf(sh1[p][g*16 + hh], __ldg(&w2[(g*16 + hh)*16 + c]), y);
        part[p] = y;
    }
    __shared__ float sh2[8][64];
#pragma unroll
    for (int p = 0; p < 8; p++) sh2[p][tid] = part[p];
    __syncthreads();
#pragma unroll
    for (int pp = g; pp < 8; pp += 4) {
        float y = sh2[pp][c] + sh2[pp][16+c] + sh2[pp][32+c] + sh2[pp][48+c];
        if (pp == 0) {
            atomicAdd(&g_out0[(s & 63)*16 + c], y);
        } else {
            int q = s * pp; int n_ = q - (q / NNODES) * NNODES;
            atomicAdd(&out[n_*NC + c], y);
        }
    }
}

// ---------------- K8: fold striped p=0 partials into logits row 0 -----------
__global__ void k8_reduce(float* __restrict__ out) {
    int c = threadIdx.x;
    if (c >= 16) return;
    float sum = 0.f;
#pragma unroll
    for (int k = 0; k < 64; k++) sum += g_out0[k*16 + c];
    out[c] += sum;
}

// ---------------- launch ----------------------------------------------------
extern "C" void kernel_launch(void* const* d_in, const int* in_sizes, int n_in,
                              void* d_out, int out_size) {
    const float* rm    = (const float*)d_in[0];
    const int*   hrow  = (const int*)  d_in[1];
    const int*   vcol  = (const int*)  d_in[4];
    const float* Wl1   = (const float*)d_in[5];
    const float* bl1   = (const float*)d_in[6];
    const float* Wl2   = (const float*)d_in[7];
    const float* bl2   = (const float*)d_in[8];
    const float* W1    = (const float*)d_in[9];
    const float* W2    = (const float*)d_in[10];
    const float* bias1 = (const float*)d_in[11];
    const float* bias2 = (const float*)d_in[12];
    float* out = (float*)d_out;

    k0_init        <<<1024, 256>>>(out, bias2, W1);
    k1_l1l2        <<<(NT + 511) / 512, 256>>>(rm, Wl1, bl1, Wl2, bl2, hrow, vcol);
    k3_scan        <<<1, 1024>>>();
    k45_scatter_inv<<<1024, 256>>>(hrow);
    k6_h           <<<NNODES, 64>>>(vcol, W1, bias1);
    k7_logits      <<<NNODES, 64>>>(vcol, W2, out);
    k8_reduce      <<<1, 16>>>(out);
}

// round 5
// speedup vs baseline: 1.0113x; 1.0113x over previous
#include <cuda_runtime.h>
#include <cuda_fp16.h>

#define NT      250000
#define NNODES  20000
#define EMB     64
#define NC      16
#define NRP     (NNODES*8)
#define W1SCALE 256.0f
#define W1INV   (1.0f/256.0f)

// ---------------- scratch ---------------------------------------------------
__device__ __align__(16) float g_l1[NT*8];       // raw l1
__device__ __align__(16) float g_l2[NT*8];       // softmaxed l2
__device__ float g_colsum[NRP];
__device__ float g_rowsum[NRP];
__device__ __align__(16) float g_invC[NRP];      // [o][p] = 1/colsum[o*p]
__device__ __align__(16) float g_invR[NRP];      // [s][p] = 1/max(rowsum[s*p],1e-6)
__device__ __align__(16) float g_h[NNODES*EMB];
__device__ __align__(16) __half2 g_w1h2[NRP*32]; // fp16 weights1 * 256, half2-packed
__device__ int   g_cnt_s[NNODES];
__device__ int   g_off_s[NNODES+1];
__device__ int   g_cur_s[NNODES];
__device__ int   g_perm_s[NT];
__device__ float g_out0[64*16];                  // striped partials for p=0 logits

// ---------------- K0: zero everything + init logits + convert W1 -> fp16 ----
__global__ void k0_init(float* __restrict__ out, const float* __restrict__ bias2,
                        const float* __restrict__ W1) {
    int i = blockIdx.x * blockDim.x + threadIdx.x;
    int stride = gridDim.x * blockDim.x;
    for (int j = i; j < NRP; j += stride) { g_colsum[j] = 0.f; g_rowsum[j] = 0.f; }
    for (int j = i; j < NNODES; j += stride) g_cnt_s[j] = 0;
    for (int j = i; j < NNODES*NC; j += stride) out[j] = bias2[j & (NC-1)];
    for (int j = i; j < 64*16; j += stride) g_out0[j] = 0.f;
    const float4* w4 = (const float4*)W1;
    for (int j = i; j < (NRP*EMB)/4; j += stride) {
        float4 w = w4[j];
        g_w1h2[j*2]   = __floats2half2_rn(w.x * W1SCALE, w.y * W1SCALE);
        g_w1h2[j*2+1] = __floats2half2_rn(w.z * W1SCALE, w.w * W1SCALE);
    }
}

// ---------------- K1: GEMMs + softmax + colsum/rowsum atomics + s-hist ------
__global__ __launch_bounds__(256) void k1_l1l2(
    const float* __restrict__ rm,
    const float* __restrict__ Wl1, const float* __restrict__ bl1,
    const float* __restrict__ Wl2, const float* __restrict__ bl2,
    const int* __restrict__ hrow, const int* __restrict__ vcol)
{
    __shared__ float4 sW14[128], sW24[128];
    __shared__ float sb1[8], sb2[8];
    int tid = threadIdx.x;
    if (tid < 128) { sW14[tid] = ((const float4*)Wl1)[tid]; sW24[tid] = ((const float4*)Wl2)[tid]; }
    if (tid < 8) { sb1[tid] = bl1[tid]; sb2[tid] = bl2[tid]; }
    __syncthreads();

    const float4* rm4 = (const float4*)rm;
    int r0 = blockIdx.x * 512 + tid;

    float a1[2][8], a2[2][8];
#pragma unroll
    for (int rr = 0; rr < 2; rr++)
#pragma unroll
        for (int p = 0; p < 8; p++) { a1[rr][p] = sb1[p]; a2[rr][p] = sb2[p]; }

    for (int k4 = 0; k4 < 16; k4++) {
        float4 x[2];
#pragma unroll
        for (int rr = 0; rr < 2; rr++) {
            int row = r0 + rr * 256;
            x[rr] = (row < NT) ? rm4[(size_t)row * 16 + k4] : make_float4(0.f,0.f,0.f,0.f);
        }
#pragma unroll
        for (int j = 0; j < 4; j++) {
            int k = k4 * 4 + j;
            float4 w1lo = sW14[k*2], w1hi = sW14[k*2+1];
            float4 w2lo = sW24[k*2], w2hi = sW24[k*2+1];
#pragma unroll
            for (int rr = 0; rr < 2; rr++) {
                float xv = (j == 0) ? x[rr].x : (j == 1) ? x[rr].y : (j == 2) ? x[rr].z : x[rr].w;
                a1[rr][0] = fmaf(xv, w1lo.x, a1[rr][0]);
                a1[rr][1] = fmaf(xv, w1lo.y, a1[rr][1]);
                a1[rr][2] = fmaf(xv, w1lo.z, a1[rr][2]);
                a1[rr][3] = fmaf(xv, w1lo.w, a1[rr][3]);
                a1[rr][4] = fmaf(xv, w1hi.x, a1[rr][4]);
                a1[rr][5] = fmaf(xv, w1hi.y, a1[rr][5]);
                a1[rr][6] = fmaf(xv, w1hi.z, a1[rr][6]);
                a1[rr][7] = fmaf(xv, w1hi.w, a1[rr][7]);
                a2[rr][0] = fmaf(xv, w2lo.x, a2[rr][0]);
                a2[rr][1] = fmaf(xv, w2lo.y, a2[rr][1]);
                a2[rr][2] = fmaf(xv, w2lo.z, a2[rr][2]);
                a2[rr][3] = fmaf(xv, w2lo.w, a2[rr][3]);
                a2[rr][4] = fmaf(xv, w2hi.x, a2[rr][4]);
                a2[rr][5] = fmaf(xv, w2hi.y, a2[rr][5]);
                a2[rr][6] = fmaf(xv, w2hi.z, a2[rr][6]);
                a2[rr][7] = fmaf(xv, w2hi.w, a2[rr][7]);
            }
        }
    }

    float p0l1 = 0.f, p0l2 = 0.f;
#pragma unroll
    for (int rr = 0; rr < 2; rr++) {
        int row = r0 + rr * 256;
        if (row >= NT) continue;
        float m = a2[rr][0];
#pragma unroll
        for (int p = 1; p < 8; p++) m = fmaxf(m, a2[rr][p]);
        float e[8], ssum = 0.f;
#pragma unroll
        for (int p = 0; p < 8; p++) { e[p] = __expf(a2[rr][p] - m); ssum += e[p]; }
        float inv = 1.f / ssum;
#pragma unroll
        for (int p = 0; p < 8; p++) e[p] *= inv;

        float4* d1 = (float4*)(g_l1 + (size_t)row * 8);
        float4* d2 = (float4*)(g_l2 + (size_t)row * 8);
        d1[0] = make_float4(a1[rr][0], a1[rr][1], a1[rr][2], a1[rr][3]);
        d1[1] = make_float4(a1[rr][4], a1[rr][5], a1[rr][6], a1[rr][7]);
        d2[0] = make_float4(e[0], e[1], e[2], e[3]);
        d2[1] = make_float4(e[4], e[5], e[6], e[7]);

        int o = vcol[row], s = hrow[row];
        p0l1 += a1[rr][0];
        p0l2 += e[0];
#pragma unroll
        for (int p = 1; p < 8; p++) {
            atomicAdd(&g_colsum[o * p], a1[rr][p]);
            atomicAdd(&g_rowsum[s * p], e[p]);
        }
        atomicAdd(&g_cnt_s[s], 1);
    }

    int lane = tid & 31, wid = tid >> 5;
#pragma unroll
    for (int d = 16; d > 0; d >>= 1) {
        p0l1 += __shfl_down_sync(0xffffffffu, p0l1, d);
        p0l2 += __shfl_down_sync(0xffffffffu, p0l2, d);
    }
    __shared__ float red1[8], red2[8];
    if (lane == 0) { red1[wid] = p0l1; red2[wid] = p0l2; }
    __syncthreads();
    if (tid == 0) {
        float s1 = 0.f, s2 = 0.f;
#pragma unroll
        for (int w = 0; w < 8; w++) { s1 += red1[w]; s2 += red2[w]; }
        atomicAdd(&g_colsum[0], s1);
        atomicAdd(&g_rowsum[0], s2);
    }
}

// ---------------- K3: fast 3-level shuffle scan (1 block) -------------------
__global__ __launch_bounds__(1024) void k3_scan() {
    int tid = threadIdx.x;
    const int CH = 20;
    int base = tid * CH;
    int loc[CH]; int sum = 0;
#pragma unroll
    for (int j = 0; j < CH; j++) {
        int idx = base + j;
        int v = (idx < NNODES) ? g_cnt_s[idx] : 0;
        loc[j] = v; sum += v;
    }
    int lane = tid & 31, wid = tid >> 5;
    int x = sum;
#pragma unroll
    for (int d = 1; d < 32; d <<= 1) {
        int y = __shfl_up_sync(0xffffffffu, x, d);
        if (lane >= d) x += y;
    }
    __shared__ int wsum[32];
    if (lane == 31) wsum[wid] = x;
    __syncthreads();
    if (wid == 0) {
        int w = wsum[lane];
#pragma unroll
        for (int d = 1; d < 32; d <<= 1) {
            int y = __shfl_up_sync(0xffffffffu, w, d);
            if (lane >= d) w += y;
        }
        wsum[lane] = w;
    }
    __syncthreads();
    int run = x - sum + (wid ? wsum[wid - 1] : 0);
#pragma unroll
    for (int j = 0; j < CH; j++) {
        int idx = base + j;
        if (idx < NNODES) { g_off_s[idx] = run; g_cur_s[idx] = run; run += loc[j]; }
    }
    if (tid == 1023) g_off_s[NNODES] = wsum[31];
}

// ---------------- K45: scatter edges into CSR + build inverse tables --------
__global__ void k45_scatter_inv(const int* __restrict__ hrow) {
    int i = blockIdx.x * blockDim.x + threadIdx.x;
    int stride = gridDim.x * blockDim.x;
    for (int t = i; t < NT; t += stride) {
        int p = atomicAdd(&g_cur_s[hrow[t]], 1);
        g_perm_s[p] = t;
    }
    for (int j = i; j < NRP; j += stride) {
        int node = j >> 3, p = j & 7;
        g_invC[j] = 1.f / g_colsum[node * p];
        g_invR[j] = 1.f / fmaxf(g_rowsum[node * p], 1e-6f);
    }
}

// ---------------- K6: h[s] = relu(bias1 + sum_{t,p} l1n * W1[o*p]) ----------
// 128 threads = 4 warps; warp-per-edge; each lane covers 2 columns via half2.
__global__ __launch_bounds__(128) void k6_h(
    const int* __restrict__ vcol, const float* __restrict__ W1,
    const float* __restrict__ bias1)
{
    int s = blockIdx.x;
    int tid = threadIdx.x, lane = tid & 31, wid = tid >> 5;
    int beg = g_off_s[s], end = g_off_s[s+1];
    __shared__ float sh_l[128][8];
    __shared__ int sh_ob[128];                   // o*32 (half2 row stride)
    float c0 = 0.f, c1 = 0.f;                    // cols lane*2, lane*2+1
    float acc0_w = 0.f;                          // warp-uniform sum of l[0]

    for (int tile = beg; tile < end; tile += 128) {
        int n = min(128, end - tile);
        if (tid < n) {
            int t = g_perm_s[tile + tid];
            int o = vcol[t];
            sh_ob[tid] = o * 32;
            const float4* lp = (const float4*)(g_l1 + (size_t)t * 8);
            const float4* ip = (const float4*)(g_invC + (size_t)o * 8);
            float4 a = lp[0], b = lp[1], ia = ip[0], ib = ip[1];
            sh_l[tid][0] = a.x * ia.x; sh_l[tid][1] = a.y * ia.y;
            sh_l[tid][2] = a.z * ia.z; sh_l[tid][3] = a.w * ia.w;
            sh_l[tid][4] = b.x * ib.x; sh_l[tid][5] = b.y * ib.y;
            sh_l[tid][6] = b.z * ib.z; sh_l[tid][7] = b.w * ib.w;
        }
        __syncthreads();
        for (int i = wid; i < n; i += 4) {
            int ob = sh_ob[i];
            acc0_w += sh_l[i][0];
            float l1v = sh_l[i][1], l2v = sh_l[i][2], l3v = sh_l[i][3], l4v = sh_l[i][4];
            float l5v = sh_l[i][5], l6v = sh_l[i][6], l7v = sh_l[i][7];
            __half2 h1 = g_w1h2[ob     + lane];
            __half2 h2 = g_w1h2[ob*2   + lane];
            __half2 h3 = g_w1h2[ob*3   + lane];
            __half2 h4 = g_w1h2[ob*4   + lane];
            __half2 h5 = g_w1h2[ob*5   + lane];
            __half2 h6 = g_w1h2[ob*6   + lane];
            __half2 h7 = g_w1h2[ob*7   + lane];
            float2 f1 = __half22float2(h1), f2 = __half22float2(h2);
            float2 f3 = __half22float2(h3), f4 = __half22float2(h4);
            float2 f5 = __half22float2(h5), f6 = __half22float2(h6);
            float2 f7 = __half22float2(h7);
            c0 = fmaf(l1v, f1.x, c0); c1 = fmaf(l1v, f1.y, c1);
            c0 = fmaf(l2v, f2.x, c0); c1 = fmaf(l2v, f2.y, c1);
            c0 = fmaf(l3v, f3.x, c0); c1 = fmaf(l3v, f3.y, c1);
            c0 = fmaf(l4v, f4.x, c0); c1 = fmaf(l4v, f4.y, c1);
            c0 = fmaf(l5v, f5.x, c0); c1 = fmaf(l5v, f5.y, c1);
            c0 = fmaf(l6v, f6.x, c0); c1 = fmaf(l6v, f6.y, c1);
            c0 = fmaf(l7v, f7.x, c0); c1 = fmaf(l7v, f7.y, c1);
        }
        __syncthreads();
    }

    __shared__ float sred[4][64];
    __shared__ float s0[4];
    sred[wid][lane*2] = c0; sred[wid][lane*2 + 1] = c1;
    if (lane == 0) s0[wid] = acc0_w;
    __syncthreads();
    if (tid < 64) {
        float acc = sred[0][tid] + sred[1][tid] + sred[2][tid] + sred[3][tid];
        float a0  = s0[0] + s0[1] + s0[2] + s0[3];
        acc = acc * W1INV + a0 * __ldg(&W1[tid]);      // p=0 weight row in fp32
        g_h[(size_t)s*64 + tid] = fmaxf(acc + bias1[tid], 0.f);
    }
}

// ---------------- K7: fused h2 + einsum -> logits ---------------------------
__global__ __launch_bounds__(64) void k7_logits(
    const int* __restrict__ vcol, const float* __restrict__ W2,
    float* __restrict__ out)
{
    int s = blockIdx.x, tid = threadIdx.x;
    int beg = g_off_s[s], end = g_off_s[s+1];
    if (beg == end) return;
    __shared__ float sh_l[64][9];
    __shared__ int sh_o[64];
    float a[8] = {0.f,0.f,0.f,0.f,0.f,0.f,0.f,0.f};
    const float4* ir = (const float4*)(g_invR + (size_t)s * 8);
    float4 ia = ir[0], ib = ir[1];
    for (int tile = beg; tile < end; tile += 64) {
        int n = min(64, end - tile);
        if (tid < n) {
            int t = g_perm_s[tile + tid];
            int o = vcol[t];
            sh_o[tid] = o;
            const float4* lp = (const float4*)(g_l2 + (size_t)t * 8);
            float4 la = lp[0], lb = lp[1];
            sh_l[tid][0] = la.x * ia.x; sh_l[tid][1] = la.y * ia.y;
            sh_l[tid][2] = la.z * ia.z; sh_l[tid][3] = la.w * ia.w;
            sh_l[tid][4] = lb.x * ib.x; sh_l[tid][5] = lb.y * ib.y;
            sh_l[tid][6] = lb.z * ib.z; sh_l[tid][7] = lb.w * ib.w;
        }
        __syncthreads();
        for (int i = 0; i < n; i++) {
            float hv = g_h[(size_t)sh_o[i]*64 + tid];
#pragma unroll
            for (int p = 0; p < 8; p++) a[p] = fmaf(sh_l[i][p], hv, a[p]);
        }
        __syncthreads();
    }
    __shared__ float sh1[8][64];
#pragma unroll
    for (int p = 0; p < 8; p++) sh1[p][tid] = a[p];
    __syncthreads();
    int g = tid >> 4, c = tid & 15;
    float part[8];
#pragma unroll
    for (int p = 0; p < 8; p++) {
        int q = s * p; int r = q / NNODES;
        const float* w2 = W2 + r * (EMB*NC);
        float y = 0.f;
#pragma unroll
        for (int hh = 0; hh < 16; hh++)
            y = fmaf(sh1[p][g*16 + hh], __ldg(&w2[(g*16 + hh)*16 + c]), y);
        part[p] = y;
    }
    __shared__ float sh2[8][64];
#pragma unroll
    for (int p = 0; p < 8; p++) sh2[p][tid] = part[p];
    __syncthreads();
#pragma unroll
    for (int pp = g; pp < 8; pp += 4) {
        float y = sh2[pp][c] + sh2[pp][16+c] + sh2[pp][32+c] + sh2[pp][48+c];
        if (pp == 0) {
            atomicAdd(&g_out0[(s & 63)*16 + c], y);
        } else {
            int q = s * pp; int n_ = q - (q / NNODES) * NNODES;
            atomicAdd(&out[n_*NC + c], y);
        }
    }
}

// ---------------- K8: fold striped p=0 partials into logits row 0 -----------
__global__ void k8_reduce(float* __restrict__ out) {
    int c = threadIdx.x;
    if (c >= 16) return;
    float sum = 0.f;
#pragma unroll
    for (int k = 0; k < 64; k++) sum += g_out0[k*16 + c];
    out[c] += sum;
}

// ---------------- launch ----------------------------------------------------
extern "C" void kernel_launch(void* const* d_in, const int* in_sizes, int n_in,
                              void* d_out, int out_size) {
    const float* rm    = (const float*)d_in[0];
    const int*   hrow  = (const int*)  d_in[1];
    const int*   vcol  = (const int*)  d_in[4];
    const float* Wl1   = (const float*)d_in[5];
    const float* bl1   = (const float*)d_in[6];
    const float* Wl2   = (const float*)d_in[7];
    const float* bl2   = (const float*)d_in[8];
    const float* W1    = (const float*)d_in[9];
    const float* W2    = (const float*)d_in[10];
    const float* bias1 = (const float*)d_in[11];
    const float* bias2 = (const float*)d_in[12];
    float* out = (float*)d_out;

    k0_init        <<<1024, 256>>>(out, bias2, W1);
    k1_l1l2        <<<(NT + 511) / 512, 256>>>(rm, Wl1, bl1, Wl2, bl2, hrow, vcol);
    k3_scan        <<<1, 1024>>>();
    k45_scatter_inv<<<1024, 256>>>(hrow);
    k6_h           <<<NNODES, 128>>>(vcol, W1, bias1);
    k7_logits      <<<NNODES, 64>>>(vcol, W2, out);
    k8_reduce      <<<1, 16>>>(out);
}

// round 7
// speedup vs baseline: 1.0659x; 1.0539x over previous
#include <cuda_runtime.h>

#define NT      250000
#define NNODES  20000
#define EMB     64
#define NC      16
#define NRP     (NNODES*8)

// ---------------- scratch ---------------------------------------------------
__device__ __align__(16) float g_l1[NT*8];       // raw l1
__device__ __align__(16) float g_l2[NT*8];       // softmaxed l2
__device__ float g_colsum[NRP];
__device__ float g_rowsum[NRP];
__device__ __align__(16) float g_invC[NRP];      // [o][p] = 1/colsum[o*p]
__device__ __align__(16) float g_invR[NRP];      // [s][p] = 1/max(rowsum[s*p],1e-6)
__device__ __align__(16) float g_h[NNODES*EMB];
__device__ int   g_cnt_s[NNODES];
__device__ int   g_off_s[NNODES+1];
__device__ int   g_cur_s[NNODES];
__device__ int   g_perm_s[NT];
__device__ float g_out0[64*16];                  // striped partials for p=0 logits

// ---------------- K0: zero everything + init logits with bias2 --------------
__global__ void k0_init(float* __restrict__ out, const float* __restrict__ bias2) {
    int i = blockIdx.x * blockDim.x + threadIdx.x;
    int stride = gridDim.x * blockDim.x;
    for (int j = i; j < NRP; j += stride) { g_colsum[j] = 0.f; g_rowsum[j] = 0.f; }
    for (int j = i; j < NNODES; j += stride) g_cnt_s[j] = 0;
    for (int j = i; j < NNODES*NC; j += stride) out[j] = bias2[j & (NC-1)];
    for (int j = i; j < 64*16; j += stride) g_out0[j] = 0.f;
}

// ---------------- K1: GEMMs + softmax + colsum/rowsum atomics + s-hist ------
__global__ __launch_bounds__(256) void k1_l1l2(
    const float* __restrict__ rm,
    const float* __restrict__ Wl1, const float* __restrict__ bl1,
    const float* __restrict__ Wl2, const float* __restrict__ bl2,
    const int* __restrict__ hrow, const int* __restrict__ vcol)
{
    __shared__ float4 sW14[128], sW24[128];
    __shared__ float sb1[8], sb2[8];
    int tid = threadIdx.x;
    if (tid < 128) { sW14[tid] = ((const float4*)Wl1)[tid]; sW24[tid] = ((const float4*)Wl2)[tid]; }
    if (tid < 8) { sb1[tid] = bl1[tid]; sb2[tid] = bl2[tid]; }
    __syncthreads();

    const float4* rm4 = (const float4*)rm;
    int r0 = blockIdx.x * 512 + tid;

    float a1[2][8], a2[2][8];
#pragma unroll
    for (int rr = 0; rr < 2; rr++)
#pragma unroll
        for (int p = 0; p < 8; p++) { a1[rr][p] = sb1[p]; a2[rr][p] = sb2[p]; }

    for (int k4 = 0; k4 < 16; k4++) {
        float4 x[2];
#pragma unroll
        for (int rr = 0; rr < 2; rr++) {
            int row = r0 + rr * 256;
            x[rr] = (row < NT) ? rm4[(size_t)row * 16 + k4] : make_float4(0.f,0.f,0.f,0.f);
        }
#pragma unroll
        for (int j = 0; j < 4; j++) {
            int k = k4 * 4 + j;
            float4 w1lo = sW14[k*2], w1hi = sW14[k*2+1];
            float4 w2lo = sW24[k*2], w2hi = sW24[k*2+1];
#pragma unroll
            for (int rr = 0; rr < 2; rr++) {
                float xv = (j == 0) ? x[rr].x : (j == 1) ? x[rr].y : (j == 2) ? x[rr].z : x[rr].w;
                a1[rr][0] = fmaf(xv, w1lo.x, a1[rr][0]);
                a1[rr][1] = fmaf(xv, w1lo.y, a1[rr][1]);
                a1[rr][2] = fmaf(xv, w1lo.z, a1[rr][2]);
                a1[rr][3] = fmaf(xv, w1lo.w, a1[rr][3]);
                a1[rr][4] = fmaf(xv, w1hi.x, a1[rr][4]);
                a1[rr][5] = fmaf(xv, w1hi.y, a1[rr][5]);
                a1[rr][6] = fmaf(xv, w1hi.z, a1[rr][6]);
                a1[rr][7] = fmaf(xv, w1hi.w, a1[rr][7]);
                a2[rr][0] = fmaf(xv, w2lo.x, a2[rr][0]);
                a2[rr][1] = fmaf(xv, w2lo.y, a2[rr][1]);
                a2[rr][2] = fmaf(xv, w2lo.z, a2[rr][2]);
                a2[rr][3] = fmaf(xv, w2lo.w, a2[rr][3]);
                a2[rr][4] = fmaf(xv, w2hi.x, a2[rr][4]);
                a2[rr][5] = fmaf(xv, w2hi.y, a2[rr][5]);
                a2[rr][6] = fmaf(xv, w2hi.z, a2[rr][6]);
                a2[rr][7] = fmaf(xv, w2hi.w, a2[rr][7]);
            }
        }
    }

    float p0l1 = 0.f, p0l2 = 0.f;
#pragma unroll
    for (int rr = 0; rr < 2; rr++) {
        int row = r0 + rr * 256;
        if (row >= NT) continue;
        float m = a2[rr][0];
#pragma unroll
        for (int p = 1; p < 8; p++) m = fmaxf(m, a2[rr][p]);
        float e[8], ssum = 0.f;
#pragma unroll
        for (int p = 0; p < 8; p++) { e[p] = __expf(a2[rr][p] - m); ssum += e[p]; }
        float inv = 1.f / ssum;
#pragma unroll
        for (int p = 0; p < 8; p++) e[p] *= inv;

        float4* d1 = (float4*)(g_l1 + (size_t)row * 8);
        float4* d2 = (float4*)(g_l2 + (size_t)row * 8);
        d1[0] = make_float4(a1[rr][0], a1[rr][1], a1[rr][2], a1[rr][3]);
        d1[1] = make_float4(a1[rr][4], a1[rr][5], a1[rr][6], a1[rr][7]);
        d2[0] = make_float4(e[0], e[1], e[2], e[3]);
        d2[1] = make_float4(e[4], e[5], e[6], e[7]);

        int o = vcol[row], s = hrow[row];
        p0l1 += a1[rr][0];
        p0l2 += e[0];
#pragma unroll
        for (int p = 1; p < 8; p++) {
            atomicAdd(&g_colsum[o * p], a1[rr][p]);
            atomicAdd(&g_rowsum[s * p], e[p]);
        }
        atomicAdd(&g_cnt_s[s], 1);
    }

    int lane = tid & 31, wid = tid >> 5;
#pragma unroll
    for (int d = 16; d > 0; d >>= 1) {
        p0l1 += __shfl_down_sync(0xffffffffu, p0l1, d);
        p0l2 += __shfl_down_sync(0xffffffffu, p0l2, d);
    }
    __shared__ float red1[8], red2[8];
    if (lane == 0) { red1[wid] = p0l1; red2[wid] = p0l2; }
    __syncthreads();
    if (tid == 0) {
        float s1 = 0.f, s2 = 0.f;
#pragma unroll
        for (int w = 0; w < 8; w++) { s1 += red1[w]; s2 += red2[w]; }
        atomicAdd(&g_colsum[0], s1);
        atomicAdd(&g_rowsum[0], s2);
    }
}

// ---------------- K3: fast 3-level shuffle scan (1 block) -------------------
__global__ __launch_bounds__(1024) void k3_scan() {
    int tid = threadIdx.x;
    const int CH = 20;
    int base = tid * CH;
    int loc[CH]; int sum = 0;
#pragma unroll
    for (int j = 0; j < CH; j++) {
        int idx = base + j;
        int v = (idx < NNODES) ? g_cnt_s[idx] : 0;
        loc[j] = v; sum += v;
    }
    int lane = tid & 31, wid = tid >> 5;
    int x = sum;
#pragma unroll
    for (int d = 1; d < 32; d <<= 1) {
        int y = __shfl_up_sync(0xffffffffu, x, d);
        if (lane >= d) x += y;
    }
    __shared__ int wsum[32];
    if (lane == 31) wsum[wid] = x;
    __syncthreads();
    if (wid == 0) {
        int w = wsum[lane];
#pragma unroll
        for (int d = 1; d < 32; d <<= 1) {
            int y = __shfl_up_sync(0xffffffffu, w, d);
            if (lane >= d) w += y;
        }
        wsum[lane] = w;
    }
    __syncthreads();
    int run = x - sum + (wid ? wsum[wid - 1] : 0);
#pragma unroll
    for (int j = 0; j < CH; j++) {
        int idx = base + j;
        if (idx < NNODES) { g_off_s[idx] = run; g_cur_s[idx] = run; run += loc[j]; }
    }
    if (tid == 1023) g_off_s[NNODES] = wsum[31];
}

// ---------------- K45: scatter edges into CSR + build inverse tables --------
__global__ void k45_scatter_inv(const int* __restrict__ hrow) {
    int i = blockIdx.x * blockDim.x + threadIdx.x;
    int stride = gridDim.x * blockDim.x;
    for (int t = i; t < NT; t += stride) {
        int p = atomicAdd(&g_cur_s[hrow[t]], 1);
        g_perm_s[p] = t;
    }
    for (int j = i; j < NRP; j += stride) {
        int node = j >> 3, p = j & 7;
        g_invC[j] = 1.f / g_colsum[node * p];
        g_invR[j] = 1.f / fmaxf(g_rowsum[node * p], 1e-6f);
    }
}

// ---------------- K6: h[s] = relu(bias1 + sum_{t,p} l1n * W1[o*p]) ----------
// 64 threads = 2 warps. Lane covers 2 cols via float2; warp0 rows {1,2,3,7},
// warp1 rows {4,5,6}; edges unrolled x2 for MLP.
__global__ __launch_bounds__(64) void k6_h(
    const int* __restrict__ vcol, const float* __restrict__ W1,
    const float* __restrict__ bias1)
{
    int s = blockIdx.x;
    int tid = threadIdx.x, lane = tid & 31, w = tid >> 5;
    int beg = g_off_s[s], end = g_off_s[s+1];
    __shared__ __align__(16) float sh_l[64][8];
    __shared__ int sh_o32[64];                   // o*32 (float2 row stride)
    const float2* W2p = (const float2*)W1;
    float c0 = 0.f, c1 = 0.f;                    // cols 2*lane, 2*lane+1
    float acc0 = 0.f;                            // p=0 (warp0 only, uniform)

    for (int tile = beg; tile < end; tile += 64) {
        int n = min(64, end - tile);
        if (tid < n) {
            int t = g_perm_s[tile + tid];
            int o = vcol[t];
            sh_o32[tid] = o * 32;
            const float4* lp = (const float4*)(g_l1 + (size_t)t * 8);
            const float4* ip = (const float4*)(g_invC + (size_t)o * 8);
            float4 a = lp[0], b = lp[1], ia = ip[0], ib = ip[1];
            float4* sl = (float4*)&sh_l[tid][0];
            sl[0] = make_float4(a.x*ia.x, a.y*ia.y, a.z*ia.z, a.w*ia.w);
            sl[1] = make_float4(b.x*ib.x, b.y*ib.y, b.z*ib.z, b.w*ib.w);
        }
        __syncthreads();
        int i = 0;
        for (; i + 1 < n; i += 2) {
            int q0 = sh_o32[i], q1 = sh_o32[i+1];
            float4 u0 = *(const float4*)&sh_l[i][0];
            float4 v0 = *(const float4*)&sh_l[i][4];
            float4 u1 = *(const float4*)&sh_l[i+1][0];
            float4 v1 = *(const float4*)&sh_l[i+1][4];
            if (w == 0) {
                float2 A0 = __ldg(&W2p[q0     + lane]);
                float2 B0 = __ldg(&W2p[q0*2   + lane]);
                float2 C0 = __ldg(&W2p[q0*3   + lane]);
                float2 D0 = __ldg(&W2p[q0*7   + lane]);
                float2 A1 = __ldg(&W2p[q1     + lane]);
                float2 B1 = __ldg(&W2p[q1*2   + lane]);
                float2 C1 = __ldg(&W2p[q1*3   + lane]);
                float2 D1 = __ldg(&W2p[q1*7   + lane]);
                acc0 += u0.x + u1.x;
                c0 = fmaf(u0.y, A0.x, c0); c1 = fmaf(u0.y, A0.y, c1);
                c0 = fmaf(u0.z, B0.x, c0); c1 = fmaf(u0.z, B0.y, c1);
                c0 = fmaf(u0.w, C0.x, c0); c1 = fmaf(u0.w, C0.y, c1);
                c0 = fmaf(v0.w, D0.x, c0); c1 = fmaf(v0.w, D0.y, c1);
                c0 = fmaf(u1.y, A1.x, c0); c1 = fmaf(u1.y, A1.y, c1);
                c0 = fmaf(u1.z, B1.x, c0); c1 = fmaf(u1.z, B1.y, c1);
                c0 = fmaf(u1.w, C1.x, c0); c1 = fmaf(u1.w, C1.y, c1);
                c0 = fmaf(v1.w, D1.x, c0); c1 = fmaf(v1.w, D1.y, c1);
            } else {
                float2 A0 = __ldg(&W2p[q0*4   + lane]);
                float2 B0 = __ldg(&W2p[q0*5   + lane]);
                float2 C0 = __ldg(&W2p[q0*6   + lane]);
                float2 A1 = __ldg(&W2p[q1*4   + lane]);
                float2 B1 = __ldg(&W2p[q1*5   + lane]);
                float2 C1 = __ldg(&W2p[q1*6   + lane]);
                c0 = fmaf(v0.x, A0.x, c0); c1 = fmaf(v0.x, A0.y, c1);
                c0 = fmaf(v0.y, B0.x, c0); c1 = fmaf(v0.y, B0.y, c1);
                c0 = fmaf(v0.z, C0.x, c0); c1 = fmaf(v0.z, C0.y, c1);
                c0 = fmaf(v1.x, A1.x, c0); c1 = fmaf(v1.x, A1.y, c1);
                c0 = fmaf(v1.y, B1.x, c0); c1 = fmaf(v1.y, B1.y, c1);
                c0 = fmaf(v1.z, C1.x, c0); c1 = fmaf(v1.z, C1.y, c1);
            }
        }
        if (i < n) {                                 // tail edge
            int q0 = sh_o32[i];
            float4 u0 = *(const float4*)&sh_l[i][0];
            float4 v0 = *(const float4*)&sh_l[i][4];
            if (w == 0) {
                float2 A0 = __ldg(&W2p[q0     + lane]);
                float2 B0 = __ldg(&W2p[q0*2   + lane]);
                float2 C0 = __ldg(&W2p[q0*3   + lane]);
                float2 D0 = __ldg(&W2p[q0*7   + lane]);
                acc0 += u0.x;
                c0 = fmaf(u0.y, A0.x, c0); c1 = fmaf(u0.y, A0.y, c1);
                c0 = fmaf(u0.z, B0.x, c0); c1 = fmaf(u0.z, B0.y, c1);
                c0 = fmaf(u0.w, C0.x, c0); c1 = fmaf(u0.w, C0.y, c1);
                c0 = fmaf(v0.w, D0.x, c0); c1 = fmaf(v0.w, D0.y, c1);
            } else {
                float2 A0 = __ldg(&W2p[q0*4   + lane]);
                float2 B0 = __ldg(&W2p[q0*5   + lane]);
                float2 C0 = __ldg(&W2p[q0*6   + lane]);
                c0 = fmaf(v0.x, A0.x, c0); c1 = fmaf(v0.x, A0.y, c1);
                c0 = fmaf(v0.y, B0.x, c0); c1 = fmaf(v0.y, B0.y, c1);
                c0 = fmaf(v0.z, C0.x, c0); c1 = fmaf(v0.z, C0.y, c1);
            }
        }
        __syncthreads();
    }

    __shared__ float sred[2][64];
    __shared__ float s0;
    sred[w][lane*2] = c0; sred[w][lane*2 + 1] = c1;
    if (tid == 0) s0 = acc0;
    __syncthreads();
    float acc = sred[0][tid] + sred[1][tid] + s0 * __ldg(&W1[tid]);
    g_h[(size_t)s*64 + tid] = fmaxf(acc + bias1[tid], 0.f);
}

// ---------------- K7: fused h2 + einsum -> logits ---------------------------
__global__ __launch_bounds__(64) void k7_logits(
    const int* __restrict__ vcol, const float* __restrict__ W2,
    float* __restrict__ out)
{
    int s = blockIdx.x, tid = threadIdx.x;
    int beg = g_off_s[s], end = g_off_s[s+1];
    if (beg == end) return;
    __shared__ __align__(16) float sh_l[64][8];
    __shared__ int sh_o[64];
    float a[8] = {0.f,0.f,0.f,0.f,0.f,0.f,0.f,0.f};
    const float4* ir = (const float4*)(g_invR + (size_t)s * 8);
    float4 ia = ir[0], ib = ir[1];
    for (int tile = beg; tile < end; tile += 64) {
        int n = min(64, end - tile);
        if (tid < n) {
            int t = g_perm_s[tile + tid];
            int o = vcol[t];
            sh_o[tid] = o;
            const float4* lp = (const float4*)(g_l2 + (size_t)t * 8);
            float4 la = lp[0], lb = lp[1];
            float4* sl = (float4*)&sh_l[tid][0];
            sl[0] = make_float4(la.x*ia.x, la.y*ia.y, la.z*ia.z, la.w*ia.w);
            sl[1] = make_float4(lb.x*ib.x, lb.y*ib.y, lb.z*ib.z, lb.w*ib.w);
        }
        __syncthreads();
        int i = 0;
        for (; i + 1 < n; i += 2) {
            float hv0 = __ldg(&g_h[(size_t)sh_o[i]  *64 + tid]);
            float hv1 = __ldg(&g_h[(size_t)sh_o[i+1]*64 + tid]);
            float4 u0 = *(const float4*)&sh_l[i][0];
            float4 v0 = *(const float4*)&sh_l[i][4];
            float4 u1 = *(const float4*)&sh_l[i+1][0];
            float4 v1 = *(const float4*)&sh_l[i+1][4];
            a[0] = fmaf(u0.x, hv0, a[0]); a[1] = fmaf(u0.y, hv0, a[1]);
            a[2] = fmaf(u0.z, hv0, a[2]); a[3] = fmaf(u0.w, hv0, a[3]);
            a[4] = fmaf(v0.x, hv0, a[4]); a[5] = fmaf(v0.y, hv0, a[5]);
            a[6] = fmaf(v0.z, hv0, a[6]); a[7] = fmaf(v0.w, hv0, a[7]);
            a[0] = fmaf(u1.x, hv1, a[0]); a[1] = fmaf(u1.y, hv1, a[1]);
            a[2] = fmaf(u1.z, hv1, a[2]); a[3] = fmaf(u1.w, hv1, a[3]);
            a[4] = fmaf(v1.x, hv1, a[4]); a[5] = fmaf(v1.y, hv1, a[5]);
            a[6] = fmaf(v1.z, hv1, a[6]); a[7] = fmaf(v1.w, hv1, a[7]);
        }
        if (i < n) {
            float hv0 = __ldg(&g_h[(size_t)sh_o[i]*64 + tid]);
            float4 u0 = *(const float4*)&sh_l[i][0];
            float4 v0 = *(const float4*)&sh_l[i][4];
            a[0] = fmaf(u0.x, hv0, a[0]); a[1] = fmaf(u0.y, hv0, a[1]);
            a[2] = fmaf(u0.z, hv0, a[2]); a[3] = fmaf(u0.w, hv0, a[3]);
            a[4] = fmaf(v0.x, hv0, a[4]); a[5] = fmaf(v0.y, hv0, a[5]);
            a[6] = fmaf(v0.z, hv0, a[6]); a[7] = fmaf(v0.w, hv0, a[7]);
        }
        __syncthreads();
    }
    __shared__ float sh1[8][64];
#pragma unroll
    for (int p = 0; p < 8; p++) sh1[p][tid] = a[p];
    __syncthreads();
    int g = tid >> 4, c = tid & 15;
    float part[8];
#pragma unroll
    for (int p = 0; p < 8; p++) {
        int q = s * p; int r = q / NNODES;
        const float* w2 = W2 + r * (EMB*NC);
        float y = 0.f;
#pragma unroll
        for (int hh = 0; hh < 16; hh++)
            y = fmaf(sh1[p][g*16 + hh], __ldg(&w2[(g*16 + hh)*16 + c]), y);
        part[p] = y;
    }
    __shared__ float sh2[8][64];
#pragma unroll
    for (int p = 0; p < 8; p++) sh2[p][tid] = part[p];
    __syncthreads();
#pragma unroll
    for (int pp = g; pp < 8; pp += 4) {
        float y = sh2[pp][c] + sh2[pp][16+c] + sh2[pp][32+c] + sh2[pp][48+c];
        if (pp == 0) {
            atomicAdd(&g_out0[(s & 63)*16 + c], y);
        } else {
            int q = s * pp; int n_ = q - (q / NNODES) * NNODES;
            atomicAdd(&out[n_*NC + c], y);
        }
    }
}

// ---------------- K8: fold striped p=0 partials into logits row 0 -----------
__global__ void k8_reduce(float* __restrict__ out) {
    int c = threadIdx.x;
    if (c >= 16) return;
    float sum = 0.f;
#pragma unroll
    for (int k = 0; k < 64; k++) sum += g_out0[k*16 + c];
    out[c] += sum;
}

// ---------------- launch ----------------------------------------------------
extern "C" void kernel_launch(void* const* d_in, const int* in_sizes, int n_in,
                              void* d_out, int out_size) {
    const float* rm    = (const float*)d_in[0];
    const int*   hrow  = (const int*)  d_in[1];
    const int*   vcol  = (const int*)  d_in[4];
    const float* Wl1   = (const float*)d_in[5];
    const float* bl1   = (const float*)d_in[6];
    const float* Wl2   = (const float*)d_in[7];
    const float* bl2   = (const float*)d_in[8];
    const float* W1    = (const float*)d_in[9];
    const float* W2    = (const float*)d_in[10];
    const float* bias1 = (const float*)d_in[11];
    const float* bias2 = (const float*)d_in[12];
    float* out = (float*)d_out;

    k0_init        <<<512, 256>>>(out, bias2);
    k1_l1l2        <<<(NT + 511) / 512, 256>>>(rm, Wl1, bl1, Wl2, bl2, hrow, vcol);
    k3_scan        <<<1, 1024>>>();
    k45_scatter_inv<<<1024, 256>>>(hrow);
    k6_h           <<<NNODES, 64>>>(vcol, W1, bias1);
    k7_logits      <<<NNODES, 64>>>(vcol, W2, out);
    k8_reduce      <<<1, 16>>>(out);
}

// round 8
// speedup vs baseline: 1.0668x; 1.0009x over previous
#include <cuda_runtime.h>

#define NT      250000
#define NNODES  20000
#define EMB     64
#define NC      16
#define NRP     (NNODES*8)

// ---------------- scratch ---------------------------------------------------
__device__ __align__(16) float g_l1[NT*8];       // raw l1
__device__ __align__(16) float g_l2[NT*8];       // softmaxed l2
__device__ float g_colsum[NRP];
__device__ float g_rowsum[NRP];
__device__ __align__(16) float g_invC[NRP];      // [o][p] = 1/colsum[o*p]
__device__ __align__(16) float g_invR[NRP];      // [s][p] = 1/max(rowsum[s*p],1e-6)
__device__ __align__(16) float g_h[NNODES*EMB];
__device__ int   g_cnt_s[NNODES];
__device__ int   g_off_s[NNODES+1];
__device__ int   g_cur_s[NNODES];
__device__ int   g_perm_s[NT];
__device__ float g_out0[64*16];                  // striped partials for p=0 logits

// ---------------- K0: zero everything + init logits with bias2 --------------
__global__ void k0_init(float* __restrict__ out, const float* __restrict__ bias2) {
    int i = blockIdx.x * blockDim.x + threadIdx.x;
    int stride = gridDim.x * blockDim.x;
    for (int j = i; j < NRP; j += stride) { g_colsum[j] = 0.f; g_rowsum[j] = 0.f; }
    for (int j = i; j < NNODES; j += stride) g_cnt_s[j] = 0;
    for (int j = i; j < NNODES*NC; j += stride) out[j] = bias2[j & (NC-1)];
    for (int j = i; j < 64*16; j += stride) g_out0[j] = 0.f;
}

// ---------------- K1: GEMMs + softmax + colsum/rowsum atomics + s-hist ------
__global__ __launch_bounds__(256) void k1_l1l2(
    const float* __restrict__ rm,
    const float* __restrict__ Wl1, const float* __restrict__ bl1,
    const float* __restrict__ Wl2, const float* __restrict__ bl2,
    const int* __restrict__ hrow, const int* __restrict__ vcol)
{
    __shared__ float4 sW14[128], sW24[128];
    __shared__ float sb1[8], sb2[8];
    int tid = threadIdx.x;
    if (tid < 128) { sW14[tid] = ((const float4*)Wl1)[tid]; sW24[tid] = ((const float4*)Wl2)[tid]; }
    if (tid < 8) { sb1[tid] = bl1[tid]; sb2[tid] = bl2[tid]; }
    __syncthreads();

    const float4* rm4 = (const float4*)rm;
    int r0 = blockIdx.x * 512 + tid;

    float a1[2][8], a2[2][8];
#pragma unroll
    for (int rr = 0; rr < 2; rr++)
#pragma unroll
        for (int p = 0; p < 8; p++) { a1[rr][p] = sb1[p]; a2[rr][p] = sb2[p]; }

    for (int k4 = 0; k4 < 16; k4++) {
        float4 x[2];
#pragma unroll
        for (int rr = 0; rr < 2; rr++) {
            int row = r0 + rr * 256;
            x[rr] = (row < NT) ? rm4[(size_t)row * 16 + k4] : make_float4(0.f,0.f,0.f,0.f);
        }
#pragma unroll
        for (int j = 0; j < 4; j++) {
            int k = k4 * 4 + j;
            float4 w1lo = sW14[k*2], w1hi = sW14[k*2+1];
            float4 w2lo = sW24[k*2], w2hi = sW24[k*2+1];
#pragma unroll
            for (int rr = 0; rr < 2; rr++) {
                float xv = (j == 0) ? x[rr].x : (j == 1) ? x[rr].y : (j == 2) ? x[rr].z : x[rr].w;
                a1[rr][0] = fmaf(xv, w1lo.x, a1[rr][0]);
                a1[rr][1] = fmaf(xv, w1lo.y, a1[rr][1]);
                a1[rr][2] = fmaf(xv, w1lo.z, a1[rr][2]);
                a1[rr][3] = fmaf(xv, w1lo.w, a1[rr][3]);
                a1[rr][4] = fmaf(xv, w1hi.x, a1[rr][4]);
                a1[rr][5] = fmaf(xv, w1hi.y, a1[rr][5]);
                a1[rr][6] = fmaf(xv, w1hi.z, a1[rr][6]);
                a1[rr][7] = fmaf(xv, w1hi.w, a1[rr][7]);
                a2[rr][0] = fmaf(xv, w2lo.x, a2[rr][0]);
                a2[rr][1] = fmaf(xv, w2lo.y, a2[rr][1]);
                a2[rr][2] = fmaf(xv, w2lo.z, a2[rr][2]);
                a2[rr][3] = fmaf(xv, w2lo.w, a2[rr][3]);
                a2[rr][4] = fmaf(xv, w2hi.x, a2[rr][4]);
                a2[rr][5] = fmaf(xv, w2hi.y, a2[rr][5]);
                a2[rr][6] = fmaf(xv, w2hi.z, a2[rr][6]);
                a2[rr][7] = fmaf(xv, w2hi.w, a2[rr][7]);
            }
        }
    }

    float p0l1 = 0.f, p0l2 = 0.f;
#pragma unroll
    for (int rr = 0; rr < 2; rr++) {
        int row = r0 + rr * 256;
        if (row >= NT) continue;
        float m = a2[rr][0];
#pragma unroll
        for (int p = 1; p < 8; p++) m = fmaxf(m, a2[rr][p]);
        float e[8], ssum = 0.f;
#pragma unroll
        for (int p = 0; p < 8; p++) { e[p] = __expf(a2[rr][p] - m); ssum += e[p]; }
        float inv = 1.f / ssum;
#pragma unroll
        for (int p = 0; p < 8; p++) e[p] *= inv;

        float4* d1 = (float4*)(g_l1 + (size_t)row * 8);
        float4* d2 = (float4*)(g_l2 + (size_t)row * 8);
        d1[0] = make_float4(a1[rr][0], a1[rr][1], a1[rr][2], a1[rr][3]);
        d1[1] = make_float4(a1[rr][4], a1[rr][5], a1[rr][6], a1[rr][7]);
        d2[0] = make_float4(e[0], e[1], e[2], e[3]);
        d2[1] = make_float4(e[4], e[5], e[6], e[7]);

        int o = vcol[row], s = hrow[row];
        p0l1 += a1[rr][0];
        p0l2 += e[0];
#pragma unroll
        for (int p = 1; p < 8; p++) {
            atomicAdd(&g_colsum[o * p], a1[rr][p]);
            atomicAdd(&g_rowsum[s * p], e[p]);
        }
        atomicAdd(&g_cnt_s[s], 1);
    }

    int lane = tid & 31, wid = tid >> 5;
#pragma unroll
    for (int d = 16; d > 0; d >>= 1) {
        p0l1 += __shfl_down_sync(0xffffffffu, p0l1, d);
        p0l2 += __shfl_down_sync(0xffffffffu, p0l2, d);
    }
    __shared__ float red1[8], red2[8];
    if (lane == 0) { red1[wid] = p0l1; red2[wid] = p0l2; }
    __syncthreads();
    if (tid == 0) {
        float s1 = 0.f, s2 = 0.f;
#pragma unroll
        for (int w = 0; w < 8; w++) { s1 += red1[w]; s2 += red2[w]; }
        atomicAdd(&g_colsum[0], s1);
        atomicAdd(&g_rowsum[0], s2);
    }
}

// ---------------- K3: fast 3-level shuffle scan (1 block) -------------------
__global__ __launch_bounds__(1024) void k3_scan() {
    int tid = threadIdx.x;
    const int CH = 20;
    int base = tid * CH;
    int loc[CH]; int sum = 0;
#pragma unroll
    for (int j = 0; j < CH; j++) {
        int idx = base + j;
        int v = (idx < NNODES) ? g_cnt_s[idx] : 0;
        loc[j] = v; sum += v;
    }
    int lane = tid & 31, wid = tid >> 5;
    int x = sum;
#pragma unroll
    for (int d = 1; d < 32; d <<= 1) {
        int y = __shfl_up_sync(0xffffffffu, x, d);
        if (lane >= d) x += y;
    }
    __shared__ int wsum[32];
    if (lane == 31) wsum[wid] = x;
    __syncthreads();
    if (wid == 0) {
        int w = wsum[lane];
#pragma unroll
        for (int d = 1; d < 32; d <<= 1) {
            int y = __shfl_up_sync(0xffffffffu, w, d);
            if (lane >= d) w += y;
        }
        wsum[lane] = w;
    }
    __syncthreads();
    int run = x - sum + (wid ? wsum[wid - 1] : 0);
#pragma unroll
    for (int j = 0; j < CH; j++) {
        int idx = base + j;
        if (idx < NNODES) { g_off_s[idx] = run; g_cur_s[idx] = run; run += loc[j]; }
    }
    if (tid == 1023) g_off_s[NNODES] = wsum[31];
}

// ---------------- K45: scatter edges into CSR + build inverse tables --------
__global__ void k45_scatter_inv(const int* __restrict__ hrow) {
    int i = blockIdx.x * blockDim.x + threadIdx.x;
    int stride = gridDim.x * blockDim.x;
    for (int t = i; t < NT; t += stride) {
        int p = atomicAdd(&g_cur_s[hrow[t]], 1);
        g_perm_s[p] = t;
    }
    for (int j = i; j < NRP; j += stride) {
        int node = j >> 3, p = j & 7;
        g_invC[j] = 1.f / g_colsum[node * p];
        g_invR[j] = 1.f / fmaxf(g_rowsum[node * p], 1e-6f);
    }
}

// ---------------- K6: h[s] = relu(bias1 + sum_{t,p} l1n * W1[o*p]) ----------
// 64 threads = 2 warps. Lane covers 2 cols via float2; warp0 rows {1,2,3,7},
// warp1 rows {4,5,6}; edges unrolled x2 for MLP.
__global__ __launch_bounds__(64) void k6_h(
    const int* __restrict__ vcol, const float* __restrict__ W1,
    const float* __restrict__ bias1)
{
    int s = blockIdx.x;
    int tid = threadIdx.x, lane = tid & 31, w = tid >> 5;
    int beg = g_off_s[s], end = g_off_s[s+1];
    __shared__ __align__(16) float sh_l[64][8];
    __shared__ int sh_o32[64];                   // o*32 (float2 row stride)
    const float2* W2p = (const float2*)W1;
    float c0 = 0.f, c1 = 0.f;                    // cols 2*lane, 2*lane+1
    float acc0 = 0.f;                            // p=0 (warp0 only, uniform)

    for (int tile = beg; tile < end; tile += 64) {
        int n = min(64, end - tile);
        if (tid < n) {
            int t = g_perm_s[tile + tid];
            int o = vcol[t];
            sh_o32[tid] = o * 32;
            const float4* lp = (const float4*)(g_l1 + (size_t)t * 8);
            const float4* ip = (const float4*)(g_invC + (size_t)o * 8);
            float4 a = lp[0], b = lp[1], ia = ip[0], ib = ip[1];
            float4* sl = (float4*)&sh_l[tid][0];
            sl[0] = make_float4(a.x*ia.x, a.y*ia.y, a.z*ia.z, a.w*ia.w);
            sl[1] = make_float4(b.x*ib.x, b.y*ib.y, b.z*ib.z, b.w*ib.w);
        }
        __syncthreads();
        int i = 0;
        for (; i + 1 < n; i += 2) {
            int q0 = sh_o32[i], q1 = sh_o32[i+1];
            float4 u0 = *(const float4*)&sh_l[i][0];
            float4 v0 = *(const float4*)&sh_l[i][4];
            float4 u1 = *(const float4*)&sh_l[i+1][0];
            float4 v1 = *(const float4*)&sh_l[i+1][4];
            if (w == 0) {
                float2 A0 = __ldg(&W2p[q0     + lane]);
                float2 B0 = __ldg(&W2p[q0*2   + lane]);
                float2 C0 = __ldg(&W2p[q0*3   + lane]);
                float2 D0 = __ldg(&W2p[q0*7   + lane]);
                float2 A1 = __ldg(&W2p[q1     + lane]);
                float2 B1 = __ldg(&W2p[q1*2   + lane]);
                float2 C1 = __ldg(&W2p[q1*3   + lane]);
                float2 D1 = __ldg(&W2p[q1*7   + lane]);
                acc0 += u0.x + u1.x;
                c0 = fmaf(u0.y, A0.x, c0); c1 = fmaf(u0.y, A0.y, c1);
                c0 = fmaf(u0.z, B0.x, c0); c1 = fmaf(u0.z, B0.y, c1);
                c0 = fmaf(u0.w, C0.x, c0); c1 = fmaf(u0.w, C0.y, c1);
                c0 = fmaf(v0.w, D0.x, c0); c1 = fmaf(v0.w, D0.y, c1);
                c0 = fmaf(u1.y, A1.x, c0); c1 = fmaf(u1.y, A1.y, c1);
                c0 = fmaf(u1.z, B1.x, c0); c1 = fmaf(u1.z, B1.y, c1);
                c0 = fmaf(u1.w, C1.x, c0); c1 = fmaf(u1.w, C1.y, c1);
                c0 = fmaf(v1.w, D1.x, c0); c1 = fmaf(v1.w, D1.y, c1);
            } else {
                float2 A0 = __ldg(&W2p[q0*4   + lane]);
                float2 B0 = __ldg(&W2p[q0*5   + lane]);
                float2 C0 = __ldg(&W2p[q0*6   + lane]);
                float2 A1 = __ldg(&W2p[q1*4   + lane]);
                float2 B1 = __ldg(&W2p[q1*5   + lane]);
                float2 C1 = __ldg(&W2p[q1*6   + lane]);
                c0 = fmaf(v0.x, A0.x, c0); c1 = fmaf(v0.x, A0.y, c1);
                c0 = fmaf(v0.y, B0.x, c0); c1 = fmaf(v0.y, B0.y, c1);
                c0 = fmaf(v0.z, C0.x, c0); c1 = fmaf(v0.z, C0.y, c1);
                c0 = fmaf(v1.x, A1.x, c0); c1 = fmaf(v1.x, A1.y, c1);
                c0 = fmaf(v1.y, B1.x, c0); c1 = fmaf(v1.y, B1.y, c1);
                c0 = fmaf(v1.z, C1.x, c0); c1 = fmaf(v1.z, C1.y, c1);
            }
        }
        if (i < n) {                                 // tail edge
            int q0 = sh_o32[i];
            float4 u0 = *(const float4*)&sh_l[i][0];
            float4 v0 = *(const float4*)&sh_l[i][4];
            if (w == 0) {
                float2 A0 = __ldg(&W2p[q0     + lane]);
                float2 B0 = __ldg(&W2p[q0*2   + lane]);
                float2 C0 = __ldg(&W2p[q0*3   + lane]);
                float2 D0 = __ldg(&W2p[q0*7   + lane]);
                acc0 += u0.x;
                c0 = fmaf(u0.y, A0.x, c0); c1 = fmaf(u0.y, A0.y, c1);
                c0 = fmaf(u0.z, B0.x, c0); c1 = fmaf(u0.z, B0.y, c1);
                c0 = fmaf(u0.w, C0.x, c0); c1 = fmaf(u0.w, C0.y, c1);
                c0 = fmaf(v0.w, D0.x, c0); c1 = fmaf(v0.w, D0.y, c1);
            } else {
                float2 A0 = __ldg(&W2p[q0*4   + lane]);
                float2 B0 = __ldg(&W2p[q0*5   + lane]);
                float2 C0 = __ldg(&W2p[q0*6   + lane]);
                c0 = fmaf(v0.x, A0.x, c0); c1 = fmaf(v0.x, A0.y, c1);
                c0 = fmaf(v0.y, B0.x, c0); c1 = fmaf(v0.y, B0.y, c1);
                c0 = fmaf(v0.z, C0.x, c0); c1 = fmaf(v0.z, C0.y, c1);
            }
        }
        __syncthreads();
    }

    __shared__ float sred[2][64];
    __shared__ float s0;
    sred[w][lane*2] = c0; sred[w][lane*2 + 1] = c1;
    if (tid == 0) s0 = acc0;
    __syncthreads();
    float acc = sred[0][tid] + sred[1][tid] + s0 * __ldg(&W1[tid]);
    g_h[(size_t)s*64 + tid] = fmaxf(acc + bias1[tid], 0.f);
}

// ---------------- K7: fused h2 + einsum -> logits ---------------------------
__global__ __launch_bounds__(64) void k7_logits(
    const int* __restrict__ vcol, const float* __restrict__ W2,
    float* __restrict__ out)
{
    int s = blockIdx.x, tid = threadIdx.x;
    int beg = g_off_s[s], end = g_off_s[s+1];
    if (beg == end) return;
    __shared__ __align__(16) float sh_l[64][8];
    __shared__ int sh_o[64];
    float a[8] = {0.f,0.f,0.f,0.f,0.f,0.f,0.f,0.f};
    const float4* ir = (const float4*)(g_invR + (size_t)s * 8);
    float4 ia = ir[0], ib = ir[1];
    for (int tile = beg; tile < end; tile += 64) {
        int n = min(64, end - tile);
        if (tid < n) {
            int t = g_perm_s[tile + tid];
            int o = vcol[t];
            sh_o[tid] = o;
            const float4* lp = (const float4*)(g_l2 + (size_t)t * 8);
            float4 la = lp[0], lb = lp[1];
            float4* sl = (float4*)&sh_l[tid][0];
            sl[0] = make_float4(la.x*ia.x, la.y*ia.y, la.z*ia.z, la.w*ia.w);
            sl[1] = make_float4(lb.x*ib.x, lb.y*ib.y, lb.z*ib.z, lb.w*ib.w);
        }
        __syncthreads();
        int i = 0;
        for (; i + 1 < n; i += 2) {
            float hv0 = __ldg(&g_h[(size_t)sh_o[i]  *64 + tid]);
            float hv1 = __ldg(&g_h[(size_t)sh_o[i+1]*64 + tid]);
            float4 u0 = *(const float4*)&sh_l[i][0];
            float4 v0 = *(const float4*)&sh_l[i][4];
            float4 u1 = *(const float4*)&sh_l[i+1][0];
            float4 v1 = *(const float4*)&sh_l[i+1][4];
            a[0] = fmaf(u0.x, hv0, a[0]); a[1] = fmaf(u0.y, hv0, a[1]);
            a[2] = fmaf(u0.z, hv0, a[2]); a[3] = fmaf(u0.w, hv0, a[3]);
            a[4] = fmaf(v0.x, hv0, a[4]); a[5] = fmaf(v0.y, hv0, a[5]);
            a[6] = fmaf(v0.z, hv0, a[6]); a[7] = fmaf(v0.w, hv0, a[7]);
            a[0] = fmaf(u1.x, hv1, a[0]); a[1] = fmaf(u1.y, hv1, a[1]);
            a[2] = fmaf(u1.z, hv1, a[2]); a[3] = fmaf(u1.w, hv1, a[3]);
            a[4] = fmaf(v1.x, hv1, a[4]); a[5] = fmaf(v1.y, hv1, a[5]);
            a[6] = fmaf(v1.z, hv1, a[6]); a[7] = fmaf(v1.w, hv1, a[7]);
        }
        if (i < n) {
            float hv0 = __ldg(&g_h[(size_t)sh_o[i]*64 + tid]);
            float4 u0 = *(const float4*)&sh_l[i][0];
            float4 v0 = *(const float4*)&sh_l[i][4];
            a[0] = fmaf(u0.x, hv0, a[0]); a[1] = fmaf(u0.y, hv0, a[1]);
            a[2] = fmaf(u0.z, hv0, a[2]); a[3] = fmaf(u0.w, hv0, a[3]);
            a[4] = fmaf(v0.x, hv0, a[4]); a[5] = fmaf(v0.y, hv0, a[5]);
            a[6] = fmaf(v0.z, hv0, a[6]); a[7] = fmaf(v0.w, hv0, a[7]);
        }
        __syncthreads();
    }
    __shared__ float sh1[8][64];
#pragma unroll
    for (int p = 0; p < 8; p++) sh1[p][tid] = a[p];
    __syncthreads();
    int g = tid >> 4, c = tid & 15;
    float part[8];
#pragma unroll
    for (int p = 0; p < 8; p++) {
        int q = s * p; int r = q / NNODES;
        const float* w2 = W2 + r * (EMB*NC);
        float y = 0.f;
#pragma unroll
        for (int hh = 0; hh < 16; hh++)
            y = fmaf(sh1[p][g*16 + hh], __ldg(&w2[(g*16 + hh)*16 + c]), y);
        part[p] = y;
    }
    __shared__ float sh2[8][64];
#pragma unroll
    for (int p = 0; p < 8; p++) sh2[p][tid] = part[p];
    __syncthreads();
#pragma unroll
    for (int pp = g; pp < 8; pp += 4) {
        float y = sh2[pp][c] + sh2[pp][16+c] + sh2[pp][32+c] + sh2[pp][48+c];
        if (pp == 0) {
            atomicAdd(&g_out0[(s & 63)*16 + c], y);
        } else {
            int q = s * pp; int n_ = q - (q / NNODES) * NNODES;
            atomicAdd(&out[n_*NC + c], y);
        }
    }
}

// ---------------- K8: fold striped p=0 partials into logits row 0 -----------
__global__ void k8_reduce(float* __restrict__ out) {
    int c = threadIdx.x;
    if (c >= 16) return;
    float sum = 0.f;
#pragma unroll
    for (int k = 0; k < 64; k++) sum += g_out0[k*16 + c];
    out[c] += sum;
}

// ---------------- launch ----------------------------------------------------
extern "C" void kernel_launch(void* const* d_in, const int* in_sizes, int n_in,
                              void* d_out, int out_size) {
    const float* rm    = (const float*)d_in[0];
    const int*   hrow  = (const int*)  d_in[1];
    const int*   vcol  = (const int*)  d_in[4];
    const float* Wl1   = (const float*)d_in[5];
    const float* bl1   = (const float*)d_in[6];
    const float* Wl2   = (const float*)d_in[7];
    const float* bl2   = (const float*)d_in[8];
    const float* W1    = (const float*)d_in[9];
    const float* W2    = (const float*)d_in[10];
    const float* bias1 = (const float*)d_in[11];
    const float* bias2 = (const float*)d_in[12];
    float* out = (float*)d_out;

    k0_init        <<<512, 256>>>(out, bias2);
    k1_l1l2        <<<(NT + 511) / 512, 256>>>(rm, Wl1, bl1, Wl2, bl2, hrow, vcol);
    k3_scan        <<<1, 1024>>>();
    k45_scatter_inv<<<1024, 256>>>(hrow);
    k6_h           <<<NNODES, 64>>>(vcol, W1, bias1);
    k7_logits      <<<NNODES, 64>>>(vcol, W2, out);
    k8_reduce      <<<1, 16>>>(out);
}